// round 7
// baseline (speedup 1.0000x reference)
#include <cuda_runtime.h>
#include <cuda_bf16.h>
#include <cstdint>
#include <cstddef>

// ---------------------------------------------------------------------------
// QuantizedLinear: out[8192,16384] = x[8192,4096] @ (Wint*scale)^T + bias
// Dual-pipe design for baseline sm_103 (no 'a' features):
//   warps 0-3 (one per SMSP): int8 dual-plane mma.sync (ALU/IDP pipe), K [0,2240)
//   warps 4-7 (one per SMSP): exact fp32 fma.rn.f32x2 (FMA pipe),      K [2240,4096)
// Both paths deliver 64 useful MACs per issue slot; running them concurrently
// on each SMSP ~doubles the issue-bound throughput of the R4 kernel.
// out = scale[n]*( rs[m]*(128*C_hi + C_lo) + F ) + bias[n]
// ---------------------------------------------------------------------------

#define MTOT 8192
#define NTOT 16384
#define KTOT 4096

#define KI_CHUNKS 35            // 35 * 64 = 2240 K on the int path
#define KFP0 2240
#define KFP  1856               // fp path K
#define FPSTAGES 116            // 116 * 16 = 1856

// int ring: 4 bufs; stage = Ahi[128x64 pad80] + Alo + Bint[64x64 pad80]
#define ROWPAD 80
#define ALO_OFF 10240
#define BI_OFF  20480
#define ISTAGE  25600
#define IRING   102400

// fp ring: 4 bufs; stage = Adup[16k x 128m dup f32x2 = 16KB] + Bfp[16k x 64n = 4KB]
#define FA_BYTES 16384
#define FSTAGE   20480
#define FRING_OFF IRING
#define SMEM_BYTES (IRING + 4 * FSTAGE)   // 184320
#define FPITCH 72                          // F staging pitch in floats

// Scratch (device globals; no allocations allowed)
static __device__ __align__(16) signed char g_xhi[(size_t)MTOT * KTOT];
static __device__ __align__(16) signed char g_xlo[(size_t)MTOT * KTOT];
static __device__ __align__(16) signed char g_w8 [(size_t)NTOT * KTOT];
static __device__ __align__(16) float g_xTd[(size_t)KFP * 2 * MTOT];  // [k][2m] duplicated
static __device__ __align__(16) float g_wT [(size_t)KFP * NTOT];      // [k][n]
static __device__ float g_rs[MTOT];

// ---------------- helpers ----------------
__device__ __forceinline__ uint32_t smem_u32(const void* p) {
    uint32_t a;
    asm("{ .reg .u64 t; cvta.to.shared.u64 t, %1; cvt.u32.u64 %0, t; }" : "=r"(a) : "l"(p));
    return a;
}
__device__ __forceinline__ void cpasync16(uint32_t dst, const void* src) {
    asm volatile("cp.async.cg.shared.global [%0], [%1], 16;" :: "r"(dst), "l"(src));
}
#define CP_COMMIT() asm volatile("cp.async.commit_group;" ::: "memory")
#define CP_WAIT2()  asm volatile("cp.async.wait_group 2;" ::: "memory")
#define BAR_INT()   asm volatile("bar.sync 1, 128;" ::: "memory")
#define BAR_FP()    asm volatile("bar.sync 2, 128;" ::: "memory")
#define BAR_JOINT() asm volatile("bar.sync 3, 256;" ::: "memory")

#define LDSM4(R, ADDR) \
    asm volatile("ldmatrix.sync.aligned.m8n8.x4.shared.b16 {%0,%1,%2,%3}, [%4];" \
        : "=r"((R)[0]), "=r"((R)[1]), "=r"((R)[2]), "=r"((R)[3]) : "r"(ADDR))

#define MMA_S8(C, A, B0, B1) \
    asm volatile("mma.sync.aligned.m16n8k32.row.col.s32.s8.s8.s32 " \
        "{%0,%1,%2,%3}, {%4,%5,%6,%7}, {%8,%9}, {%0,%1,%2,%3};" \
        : "+r"((C)[0]), "+r"((C)[1]), "+r"((C)[2]), "+r"((C)[3]) \
        : "r"((A)[0]), "r"((A)[1]), "r"((A)[2]), "r"((A)[3]), "r"(B0), "r"(B1))

#define FFMA2(D, A, B) \
    asm volatile("fma.rn.f32x2 %0, %1, %2, %0;" : "+l"(D) : "l"(A), "l"(B))

#define LDS_V2U64(D0, D1, ADDR) \
    asm volatile("ld.shared.v2.u64 {%0,%1}, [%2];" : "=l"(D0), "=l"(D1) : "r"(ADDR))

#define STS_U64(ADDR, V) \
    asm volatile("st.shared.b64 [%0], %1;" :: "r"(ADDR), "l"(V) : "memory")

__device__ __forceinline__ uint32_t pack4(int b0, int b1, int b2, int b3) {
    return (uint32_t)(uint8_t)(signed char)b0 |
           ((uint32_t)(uint8_t)(signed char)b1 << 8) |
           ((uint32_t)(uint8_t)(signed char)b2 << 16) |
           ((uint32_t)(uint8_t)(signed char)b3 << 24);
}

// ---------------- Prepass: x -> per-row 15-bit (hi,lo) int8 ----------------
__global__ void __launch_bounds__(256) quant_x_kernel(const float4* __restrict__ x) {
    __shared__ float red[8];
    __shared__ float s_inv;
    const int m = blockIdx.x;
    const int t = threadIdx.x;
    const float4* row = x + (size_t)m * (KTOT / 4);

    float4 v[4];
    float mx = 0.f;
#pragma unroll
    for (int j = 0; j < 4; ++j) {
        v[j] = row[t + 256 * j];
        mx = fmaxf(mx, fmaxf(fmaxf(fabsf(v[j].x), fabsf(v[j].y)),
                             fmaxf(fabsf(v[j].z), fabsf(v[j].w))));
    }
#pragma unroll
    for (int o = 16; o > 0; o >>= 1) mx = fmaxf(mx, __shfl_xor_sync(0xffffffffu, mx, o));
    if ((t & 31) == 0) red[t >> 5] = mx;
    __syncthreads();
    if (t == 0) {
        float m2 = red[0];
#pragma unroll
        for (int wme = 1; wme < 8; ++wme) m2 = fmaxf(m2, red[wme]);
        s_inv = (m2 > 0.f) ? (16256.f / m2) : 0.f;
        g_rs[m] = m2 * (1.f / 16256.f);
    }
    __syncthreads();
    const float inv = s_inv;

    uint32_t* ohi = reinterpret_cast<uint32_t*>(g_xhi + (size_t)m * KTOT);
    uint32_t* olo = reinterpret_cast<uint32_t*>(g_xlo + (size_t)m * KTOT);
#pragma unroll
    for (int j = 0; j < 4; ++j) {
        const float f[4] = {v[j].x, v[j].y, v[j].z, v[j].w};
        int hi[4], lo[4];
#pragma unroll
        for (int e = 0; e < 4; ++e) {
            int iv = __float2int_rn(f[e] * inv);          // |iv| <= 16256
            hi[e] = (iv + 64) >> 7;                        // in [-127,127]
            lo[e] = iv - (hi[e] << 7);                     // in [-64,63]
        }
        ohi[t + 256 * j] = pack4(hi[0], hi[1], hi[2], hi[3]);
        olo[t + 256 * j] = pack4(lo[0], lo[1], lo[2], lo[3]);
    }
}

// ---------------- Prepass: W int32 -> int8 (exact) ----------------
__global__ void __launch_bounds__(256) quant_w_kernel(const int4* __restrict__ w) {
    const size_t g = (size_t)blockIdx.x * 256 + threadIdx.x;
    int4 a = w[g * 4 + 0], b = w[g * 4 + 1], c = w[g * 4 + 2], d = w[g * 4 + 3];
    uint4 o;
    o.x = pack4(a.x, a.y, a.z, a.w);
    o.y = pack4(b.x, b.y, b.z, b.w);
    o.z = pack4(c.x, c.y, c.z, c.w);
    o.w = pack4(d.x, d.y, d.z, d.w);
    reinterpret_cast<uint4*>(g_w8)[g] = o;
}

// ---------------- Prepass: x[:, 2240:4096] -> transposed + duplicated fp32 ----------------
__global__ void __launch_bounds__(256) trans_xd_kernel(const float* __restrict__ x) {
    __shared__ float t[32][33];
    const int tx = threadIdx.x & 31, ty = threadIdx.x >> 5;
    const int k0 = blockIdx.x * 32;            // rel k in [0, KFP)
    const int m0 = blockIdx.y * 32;
#pragma unroll
    for (int j = 0; j < 4; ++j)
        t[ty + 8 * j][tx] = x[(size_t)(m0 + ty + 8 * j) * KTOT + KFP0 + k0 + tx];
    __syncthreads();
#pragma unroll
    for (int j = 0; j < 4; ++j) {
        const int kr = k0 + ty + 8 * j;
        const float v = t[tx][ty + 8 * j];
        reinterpret_cast<float2*>(g_xTd)[(size_t)kr * MTOT + (m0 + tx)] = make_float2(v, v);
    }
}

// ---------------- Prepass: W[:, 2240:4096] -> transposed fp32 ----------------
__global__ void __launch_bounds__(256) trans_w_kernel(const int* __restrict__ wint) {
    __shared__ float t[32][33];
    const int tx = threadIdx.x & 31, ty = threadIdx.x >> 5;
    const int k0 = blockIdx.x * 32;
    const int n0 = blockIdx.y * 32;
#pragma unroll
    for (int j = 0; j < 4; ++j)
        t[ty + 8 * j][tx] = (float)wint[(size_t)(n0 + ty + 8 * j) * KTOT + KFP0 + k0 + tx];
    __syncthreads();
#pragma unroll
    for (int j = 0; j < 4; ++j)
        g_wT[(size_t)(k0 + ty + 8 * j) * NTOT + n0 + tx] = t[tx][ty + 8 * j];
}

// ---------------- Main dual-pipe GEMM: CTA 128m x 64n, 8 warps ----------------
__global__ void __launch_bounds__(256, 1) qlin_dual(
    float* __restrict__ out, const float* __restrict__ scale, const float* __restrict__ bias)
{
    extern __shared__ char smem[];
    const uint32_t sb = smem_u32(smem);
    const int tid  = threadIdx.x;
    const int wid  = tid >> 5;
    const int lane = tid & 31;

    // raster: bands of 8 tm x 256 tn
    const int band = blockIdx.x >> 11;
    const int w    = blockIdx.x & 2047;
    const int tm   = band * 8 + (w & 7);      // 0..63
    const int tn   = w >> 3;                  // 0..255

    if (wid < 4) {
        // ================= INT GROUP (warps 0-3) =================
        const int warpM = wid;
        const int ti = tid;                       // 0..127
        const int rowB = ti >> 1;
        const uint32_t chB = (uint32_t)(ti & 1) * 32u;
        const signed char* pAhi = g_xhi + (size_t)(tm * 128 + ti) * KTOT;
        const signed char* pAlo = g_xlo + (size_t)(tm * 128 + ti) * KTOT;
        const signed char* pB   = g_w8  + (size_t)(tn * 64 + rowB) * KTOT + chB;
        const uint32_t dA = (uint32_t)ti * ROWPAD;
        const uint32_t dB = BI_OFF + (uint32_t)rowB * ROWPAD + chB;

#define ILOAD(J) do { \
        const uint32_t st_ = sb + ((J) & 3) * ISTAGE; \
        const int ko_ = (J) * 64; \
        cpasync16(st_ + dA +  0, pAhi + ko_ +  0); \
        cpasync16(st_ + dA + 16, pAhi + ko_ + 16); \
        cpasync16(st_ + dA + 32, pAhi + ko_ + 32); \
        cpasync16(st_ + dA + 48, pAhi + ko_ + 48); \
        cpasync16(st_ + ALO_OFF + dA +  0, pAlo + ko_ +  0); \
        cpasync16(st_ + ALO_OFF + dA + 16, pAlo + ko_ + 16); \
        cpasync16(st_ + ALO_OFF + dA + 32, pAlo + ko_ + 32); \
        cpasync16(st_ + ALO_OFF + dA + 48, pAlo + ko_ + 48); \
        cpasync16(st_ + dB,      pB + ko_); \
        cpasync16(st_ + dB + 16, pB + ko_ + 16); \
        CP_COMMIT(); \
    } while (0)

        const uint32_t aoffs = (uint32_t)(warpM * 32 + (lane & 15)) * ROWPAD
                             + (uint32_t)((lane >> 4) * 16);
        const uint32_t boffs = BI_OFF
                             + (uint32_t)((lane & 7) + ((lane >> 4) << 3)) * ROWPAD
                             + (uint32_t)(((lane >> 3) & 1) * 16);

        int acch[2][8][4], accl[2][8][4];
#pragma unroll
        for (int im = 0; im < 2; ++im)
#pragma unroll
            for (int jn = 0; jn < 8; ++jn)
#pragma unroll
                for (int r = 0; r < 4; ++r) { acch[im][jn][r] = 0; accl[im][jn][r] = 0; }

        ILOAD(0);
        ILOAD(1);

#pragma unroll 1
        for (int i = 0; i < KI_CHUNKS; ++i) {
            if (i + 2 < KI_CHUNKS) { ILOAD(i + 2); } else { CP_COMMIT(); }
            CP_WAIT2();
            BAR_INT();
            const uint32_t stg = sb + (i & 3) * ISTAGE;
#pragma unroll
            for (int kk = 0; kk < 2; ++kk) {
                uint32_t ah[2][4], al[2][4], bf[4][4];
                LDSM4(ah[0], stg + aoffs + kk * 32);
                LDSM4(ah[1], stg + aoffs + 16 * ROWPAD + kk * 32);
                LDSM4(al[0], stg + ALO_OFF + aoffs + kk * 32);
                LDSM4(al[1], stg + ALO_OFF + aoffs + 16 * ROWPAD + kk * 32);
#pragma unroll
                for (int j2 = 0; j2 < 4; ++j2)
                    LDSM4(bf[j2], stg + boffs + (uint32_t)(j2 * 16 * ROWPAD) + kk * 32);
#pragma unroll
                for (int im = 0; im < 2; ++im)
#pragma unroll
                    for (int j2 = 0; j2 < 4; ++j2) {
                        MMA_S8(acch[im][2 * j2],     ah[im], bf[j2][0], bf[j2][1]);
                        MMA_S8(acch[im][2 * j2 + 1], ah[im], bf[j2][2], bf[j2][3]);
                        MMA_S8(accl[im][2 * j2],     al[im], bf[j2][0], bf[j2][1]);
                        MMA_S8(accl[im][2 * j2 + 1], al[im], bf[j2][2], bf[j2][3]);
                    }
            }
        }
#undef ILOAD

        BAR_JOINT();   // fp warps have written F staging by now

        // ---- epilogue: out = scale*(rs*(128*hi+lo) + F) + bias ----
        const float* Fst = reinterpret_cast<const float*>(smem + IRING);
        const int ml0 = warpM * 32 + (lane >> 2);
        const int ncl = (lane & 3) * 2;
#pragma unroll
        for (int im = 0; im < 2; ++im) {
            const int mla = ml0 + im * 16;
            const int r0 = tm * 128 + mla;
            const int r1 = r0 + 8;
            const float rs0 = g_rs[r0];
            const float rs1 = g_rs[r1];
            float* o0 = out + (size_t)r0 * NTOT;
            float* o1 = out + (size_t)r1 * NTOT;
#pragma unroll
            for (int jn = 0; jn < 8; ++jn) {
                const int cl = ncl + jn * 8;
                const int c  = tn * 64 + cl;
                const float s0 = __ldg(scale + c), s1 = __ldg(scale + c + 1);
                const float b0 = __ldg(bias + c),  b1 = __ldg(bias + c + 1);
                const float2 F0 = *reinterpret_cast<const float2*>(Fst + mla * FPITCH + cl);
                const float2 F1 = *reinterpret_cast<const float2*>(Fst + (mla + 8) * FPITCH + cl);
                float2 v0, v1;
                v0.x = fmaf(s0, fmaf(rs0, fmaf(128.f, (float)acch[im][jn][0], (float)accl[im][jn][0]), F0.x), b0);
                v0.y = fmaf(s1, fmaf(rs0, fmaf(128.f, (float)acch[im][jn][1], (float)accl[im][jn][1]), F0.y), b1);
                v1.x = fmaf(s0, fmaf(rs1, fmaf(128.f, (float)acch[im][jn][2], (float)accl[im][jn][2]), F1.x), b0);
                v1.y = fmaf(s1, fmaf(rs1, fmaf(128.f, (float)acch[im][jn][3], (float)accl[im][jn][3]), F1.y), b1);
                *reinterpret_cast<float2*>(o0 + c) = v0;
                *reinterpret_cast<float2*>(o1 + c) = v1;
            }
        }
    } else {
        // ================= FP GROUP (warps 4-7) =================
        const int f  = wid - 4;
        const int tf = tid - 128;                 // 0..127
        const int krow = tf >> 3;                 // 0..15
        const int sub  = tf & 7;                  // 0..7
        const float* pA = g_xTd + (size_t)krow * 16384 + (size_t)tm * 256 + sub * 32;
        const float* pB = g_wT  + (size_t)krow * NTOT  + (size_t)tn * 64  + sub * 8;
        const uint32_t sdA = (uint32_t)krow * 1024 + (uint32_t)sub * 128;
        const uint32_t sdB = FA_BYTES + (uint32_t)krow * 256 + (uint32_t)sub * 32;

#define FLOAD(J) do { \
        const uint32_t st_ = sb + FRING_OFF + ((J) & 3) * FSTAGE; \
        const float* gA_ = pA + (size_t)(J) * 262144; \
        const float* gB_ = pB + (size_t)(J) * 262144; \
        _Pragma("unroll") \
        for (int c = 0; c < 8; ++c) cpasync16(st_ + sdA + c * 16, gA_ + c * 4); \
        cpasync16(st_ + sdB,      gB_); \
        cpasync16(st_ + sdB + 16, gB_ + 4); \
        CP_COMMIT(); \
    } while (0)

        const int mg = lane >> 3;                 // 0..3
        const int ng = lane & 7;                  // 0..7
        const uint32_t aoff = (uint32_t)f * 256 + (uint32_t)mg * 64;
        const uint32_t boff = FA_BYTES + (uint32_t)ng * 32;

        uint64_t acc[8][4];
#pragma unroll
        for (int mi = 0; mi < 8; ++mi)
#pragma unroll
            for (int nj = 0; nj < 4; ++nj) acc[mi][nj] = 0ull;

        FLOAD(0);
        FLOAD(1);

#pragma unroll 1
        for (int s = 0; s < FPSTAGES; ++s) {
            if (s + 2 < FPSTAGES) { FLOAD(s + 2); } else { CP_COMMIT(); }
            CP_WAIT2();
            BAR_FP();
            const uint32_t stF = sb + FRING_OFF + (s & 3) * FSTAGE;
#pragma unroll
            for (int kk = 0; kk < 16; ++kk) {
                uint64_t a[8], b[4];
                const uint32_t ab = stF + (uint32_t)kk * 1024 + aoff;
                const uint32_t bb = stF + (uint32_t)kk * 256 + boff;
                LDS_V2U64(a[0], a[1], ab);
                LDS_V2U64(a[2], a[3], ab + 16);
                LDS_V2U64(a[4], a[5], ab + 32);
                LDS_V2U64(a[6], a[7], ab + 48);
                LDS_V2U64(b[0], b[1], bb);
                LDS_V2U64(b[2], b[3], bb + 16);
#pragma unroll
                for (int mi = 0; mi < 8; ++mi)
#pragma unroll
                    for (int nj = 0; nj < 4; ++nj)
                        FFMA2(acc[mi][nj], a[mi], b[nj]);
            }
        }
#undef FLOAD

        // ---- write F partials to staging (pitch 72 floats) ----
#pragma unroll
        for (int mi = 0; mi < 8; ++mi) {
            const uint32_t rbase = sb + IRING
                + (uint32_t)((f * 32 + mg * 8 + mi) * FPITCH + ng * 8) * 4;
#pragma unroll
            for (int nj = 0; nj < 4; ++nj)
                STS_U64(rbase + (uint32_t)nj * 8, acc[mi][nj]);
        }
        BAR_JOINT();
    }
}

// ---------------- Launch ----------------
extern "C" void kernel_launch(void* const* d_in, const int* in_sizes, int n_in,
                              void* d_out, int out_size) {
    (void)in_sizes; (void)n_in; (void)out_size;
    const float* x     = (const float*)d_in[0];   // [4,2048,4096] fp32
    const int*   wint  = (const int*)d_in[1];     // [16384,4096] int32
    const float* scale = (const float*)d_in[2];   // [16384,1] fp32
    const float* bias  = (const float*)d_in[3];   // [16384] fp32
    float* out = (float*)d_out;                   // [4,2048,16384] fp32

    quant_x_kernel<<<MTOT, 256>>>((const float4*)x);
    quant_w_kernel<<<(int)((size_t)NTOT * KTOT / 16 / 256), 256>>>((const int4*)wint);
    {
        dim3 g(KFP / 32, MTOT / 32);
        trans_xd_kernel<<<g, 256>>>(x);
    }
    {
        dim3 g(KFP / 32, NTOT / 32);
        trans_w_kernel<<<g, 256>>>(wint);
    }

    cudaFuncSetAttribute(qlin_dual, cudaFuncAttributeMaxDynamicSharedMemorySize, SMEM_BYTES);
    qlin_dual<<<(MTOT / 128) * (NTOT / 64), 256, SMEM_BYTES>>>(out, scale, bias);
}

// round 9
// speedup vs baseline: 1.2025x; 1.2025x over previous
#include <cuda_runtime.h>
#include <cuda_bf16.h>
#include <cstdint>
#include <cstddef>

// ---------------------------------------------------------------------------
// QuantizedLinear: out[8192,16384] = x[8192,4096] @ (Wint*scale)^T + bias
// Dual-pipe v2 for baseline sm_103:
//   warps 0-3: int8 dual-plane mma.sync (IDP/ALU pipe), K [0,2816)
//   warps 4-7: exact fp32 fma.rn.f32x2 with K-PAIR packing (FMA pipe), K [2816,4096)
// f32x2 reduces over k (acc.x even-k sum, acc.y odd-k sum; hadd at end)
// -> 1.0 B/MAC smem traffic, under the 128 B/cyc crossbar cap.
// out = scale[n]*( rs[m]*(128*C_hi + C_lo) + F ) + bias[n]
// ---------------------------------------------------------------------------

#define MTOT 8192
#define NTOT 16384
#define KTOT 4096

#define KI_CHUNKS 44            // 44 * 64 = 2816 K on the int path
#define KFP0 2816
#define KFP  1280               // fp path K (640 k-pairs)
#define FPSTAGES 80             // 80 stages * 16 k (8 k-pairs)

// int ring: 4 bufs; stage = Ahi[128x64 pad80] + Alo + Bint[64x64 pad80]
#define ROWPAD 80
#define ALO_OFF 10240
#define BI_OFF  20480
#define ISTAGE  25600
#define IRING   102400

// fp ring: 4 bufs; stage = Apair[8kp x 128m x 8B = 8KB] + Bpair[8kp x 64n x 8B = 4KB]
#define FA_BYTES 8192
#define FSTAGE   12288
#define FRING_OFF IRING
#define SMEM_BYTES (IRING + 4 * FSTAGE)   // 151552
#define FPITCH 72                          // F staging pitch in floats (36864 B < fp ring)

// Scratch (device globals; no allocations allowed)
static __device__ __align__(16) signed char g_xhi[(size_t)MTOT * KTOT];
static __device__ __align__(16) signed char g_xlo[(size_t)MTOT * KTOT];
static __device__ __align__(16) signed char g_w8 [(size_t)NTOT * KTOT];
static __device__ __align__(16) float2 g_xp[(size_t)(KFP / 2) * MTOT];  // [kp][m] (k even, k odd)
static __device__ __align__(16) float2 g_wp[(size_t)(KFP / 2) * NTOT];  // [kp][n]
static __device__ float g_rs[MTOT];

// ---------------- helpers ----------------
__device__ __forceinline__ uint32_t smem_u32(const void* p) {
    uint32_t a;
    asm("{ .reg .u64 t; cvta.to.shared.u64 t, %1; cvt.u32.u64 %0, t; }" : "=r"(a) : "l"(p));
    return a;
}
__device__ __forceinline__ void cpasync16(uint32_t dst, const void* src) {
    asm volatile("cp.async.cg.shared.global [%0], [%1], 16;" :: "r"(dst), "l"(src));
}
#define CP_COMMIT() asm volatile("cp.async.commit_group;" ::: "memory")
#define CP_WAIT2()  asm volatile("cp.async.wait_group 2;" ::: "memory")
#define BAR_INT()   asm volatile("bar.sync 1, 128;" ::: "memory")
#define BAR_FP()    asm volatile("bar.sync 2, 128;" ::: "memory")
#define BAR_JOINT() asm volatile("bar.sync 3, 256;" ::: "memory")

#define LDSM4(R, ADDR) \
    asm volatile("ldmatrix.sync.aligned.m8n8.x4.shared.b16 {%0,%1,%2,%3}, [%4];" \
        : "=r"((R)[0]), "=r"((R)[1]), "=r"((R)[2]), "=r"((R)[3]) : "r"(ADDR))

#define MMA_S8(C, A, B0, B1) \
    asm volatile("mma.sync.aligned.m16n8k32.row.col.s32.s8.s8.s32 " \
        "{%0,%1,%2,%3}, {%4,%5,%6,%7}, {%8,%9}, {%0,%1,%2,%3};" \
        : "+r"((C)[0]), "+r"((C)[1]), "+r"((C)[2]), "+r"((C)[3]) \
        : "r"((A)[0]), "r"((A)[1]), "r"((A)[2]), "r"((A)[3]), "r"(B0), "r"(B1))

#define FFMA2(D, A, B) \
    asm volatile("fma.rn.f32x2 %0, %1, %2, %0;" : "+l"(D) : "l"(A), "l"(B))

#define LDS_V2U64(D0, D1, ADDR) \
    asm volatile("ld.shared.v2.u64 {%0,%1}, [%2];" : "=l"(D0), "=l"(D1) : "r"(ADDR))
#define LDS_U64(D, ADDR) \
    asm volatile("ld.shared.b64 %0, [%1];" : "=l"(D) : "r"(ADDR))
#define STS_F32(ADDR, V) \
    asm volatile("st.shared.f32 [%0], %1;" :: "r"(ADDR), "f"(V) : "memory")
#define UNPACK2(LO, HI, V) \
    asm volatile("mov.b64 {%0,%1}, %2;" : "=f"(LO), "=f"(HI) : "l"(V))

__device__ __forceinline__ uint32_t pack4(int b0, int b1, int b2, int b3) {
    return (uint32_t)(uint8_t)(signed char)b0 |
           ((uint32_t)(uint8_t)(signed char)b1 << 8) |
           ((uint32_t)(uint8_t)(signed char)b2 << 16) |
           ((uint32_t)(uint8_t)(signed char)b3 << 24);
}

// ---------------- Prepass: x -> per-row 15-bit (hi,lo) int8 ----------------
__global__ void __launch_bounds__(256) quant_x_kernel(const float4* __restrict__ x) {
    __shared__ float red[8];
    __shared__ float s_inv;
    const int m = blockIdx.x;
    const int t = threadIdx.x;
    const float4* row = x + (size_t)m * (KTOT / 4);

    float4 v[4];
    float mx = 0.f;
#pragma unroll
    for (int j = 0; j < 4; ++j) {
        v[j] = row[t + 256 * j];
        mx = fmaxf(mx, fmaxf(fmaxf(fabsf(v[j].x), fabsf(v[j].y)),
                             fmaxf(fabsf(v[j].z), fabsf(v[j].w))));
    }
#pragma unroll
    for (int o = 16; o > 0; o >>= 1) mx = fmaxf(mx, __shfl_xor_sync(0xffffffffu, mx, o));
    if ((t & 31) == 0) red[t >> 5] = mx;
    __syncthreads();
    if (t == 0) {
        float m2 = red[0];
#pragma unroll
        for (int wme = 1; wme < 8; ++wme) m2 = fmaxf(m2, red[wme]);
        s_inv = (m2 > 0.f) ? (16256.f / m2) : 0.f;
        g_rs[m] = m2 * (1.f / 16256.f);
    }
    __syncthreads();
    const float inv = s_inv;

    uint32_t* ohi = reinterpret_cast<uint32_t*>(g_xhi + (size_t)m * KTOT);
    uint32_t* olo = reinterpret_cast<uint32_t*>(g_xlo + (size_t)m * KTOT);
#pragma unroll
    for (int j = 0; j < 4; ++j) {
        const float f[4] = {v[j].x, v[j].y, v[j].z, v[j].w};
        int hi[4], lo[4];
#pragma unroll
        for (int e = 0; e < 4; ++e) {
            int iv = __float2int_rn(f[e] * inv);          // |iv| <= 16256
            hi[e] = (iv + 64) >> 7;                        // in [-127,127]
            lo[e] = iv - (hi[e] << 7);                     // in [-64,63]
        }
        ohi[t + 256 * j] = pack4(hi[0], hi[1], hi[2], hi[3]);
        olo[t + 256 * j] = pack4(lo[0], lo[1], lo[2], lo[3]);
    }
}

// ---------------- Prepass: W int32 -> int8 (exact) ----------------
__global__ void __launch_bounds__(256) quant_w_kernel(const int4* __restrict__ w) {
    const size_t g = (size_t)blockIdx.x * 256 + threadIdx.x;
    int4 a = w[g * 4 + 0], b = w[g * 4 + 1], c = w[g * 4 + 2], d = w[g * 4 + 3];
    uint4 o;
    o.x = pack4(a.x, a.y, a.z, a.w);
    o.y = pack4(b.x, b.y, b.z, b.w);
    o.z = pack4(c.x, c.y, c.z, c.w);
    o.w = pack4(d.x, d.y, d.z, d.w);
    reinterpret_cast<uint4*>(g_w8)[g] = o;
}

// ---------------- Prepass: x[:, 2816:4096] -> [kp][m] k-pair fp32 ----------------
__global__ void __launch_bounds__(256) trans_xp_kernel(const float* __restrict__ x) {
    __shared__ float t[32][33];              // t[m_local][k_local]
    const int tx = threadIdx.x & 31, ty = threadIdx.x >> 5;
    const int k0 = blockIdx.x * 32;          // rel k in [0, KFP)
    const int m0 = blockIdx.y * 32;
#pragma unroll
    for (int j = 0; j < 4; ++j)
        t[ty + 8 * j][tx] = x[(size_t)(m0 + ty + 8 * j) * KTOT + KFP0 + k0 + tx];
    __syncthreads();
#pragma unroll
    for (int j = 0; j < 2; ++j) {
        const int kpl = ty + 8 * j;          // 0..15
        const float v0 = t[tx][2 * kpl];
        const float v1 = t[tx][2 * kpl + 1];
        g_xp[(size_t)(k0 / 2 + kpl) * MTOT + m0 + tx] = make_float2(v0, v1);
    }
}

// ---------------- Prepass: W[:, 2816:4096] -> [kp][n] k-pair fp32 ----------------
__global__ void __launch_bounds__(256) trans_wp_kernel(const int* __restrict__ wint) {
    __shared__ float t[32][33];
    const int tx = threadIdx.x & 31, ty = threadIdx.x >> 5;
    const int k0 = blockIdx.x * 32;
    const int n0 = blockIdx.y * 32;
#pragma unroll
    for (int j = 0; j < 4; ++j)
        t[ty + 8 * j][tx] = (float)wint[(size_t)(n0 + ty + 8 * j) * KTOT + KFP0 + k0 + tx];
    __syncthreads();
#pragma unroll
    for (int j = 0; j < 2; ++j) {
        const int kpl = ty + 8 * j;
        const float v0 = t[tx][2 * kpl];
        const float v1 = t[tx][2 * kpl + 1];
        g_wp[(size_t)(k0 / 2 + kpl) * NTOT + n0 + tx] = make_float2(v0, v1);
    }
}

// ---------------- Main dual-pipe GEMM: CTA 128m x 64n, 8 warps ----------------
__global__ void __launch_bounds__(256, 1) qlin_dual(
    float* __restrict__ out, const float* __restrict__ scale, const float* __restrict__ bias)
{
    extern __shared__ char smem[];
    const uint32_t sb = smem_u32(smem);
    const int tid  = threadIdx.x;
    const int wid  = tid >> 5;
    const int lane = tid & 31;

    // raster: bands of 8 tm x 256 tn
    const int band = blockIdx.x >> 11;
    const int w    = blockIdx.x & 2047;
    const int tm   = band * 8 + (w & 7);      // 0..63
    const int tn   = w >> 3;                  // 0..255

    if (wid < 4) {
        // ================= INT GROUP (warps 0-3), K [0, 2816) =================
        const int warpM = wid;
        const int ti = tid;                       // 0..127
        const int rowB = ti >> 1;
        const uint32_t chB = (uint32_t)(ti & 1) * 32u;
        const signed char* pAhi = g_xhi + (size_t)(tm * 128 + ti) * KTOT;
        const signed char* pAlo = g_xlo + (size_t)(tm * 128 + ti) * KTOT;
        const signed char* pB   = g_w8  + (size_t)(tn * 64 + rowB) * KTOT + chB;
        const uint32_t dA = (uint32_t)ti * ROWPAD;
        const uint32_t dB = BI_OFF + (uint32_t)rowB * ROWPAD + chB;

#define ILOAD(J) do { \
        const uint32_t st_ = sb + ((J) & 3) * ISTAGE; \
        const int ko_ = (J) * 64; \
        cpasync16(st_ + dA +  0, pAhi + ko_ +  0); \
        cpasync16(st_ + dA + 16, pAhi + ko_ + 16); \
        cpasync16(st_ + dA + 32, pAhi + ko_ + 32); \
        cpasync16(st_ + dA + 48, pAhi + ko_ + 48); \
        cpasync16(st_ + ALO_OFF + dA +  0, pAlo + ko_ +  0); \
        cpasync16(st_ + ALO_OFF + dA + 16, pAlo + ko_ + 16); \
        cpasync16(st_ + ALO_OFF + dA + 32, pAlo + ko_ + 32); \
        cpasync16(st_ + ALO_OFF + dA + 48, pAlo + ko_ + 48); \
        cpasync16(st_ + dB,      pB + ko_); \
        cpasync16(st_ + dB + 16, pB + ko_ + 16); \
        CP_COMMIT(); \
    } while (0)

        const uint32_t aoffs = (uint32_t)(warpM * 32 + (lane & 15)) * ROWPAD
                             + (uint32_t)((lane >> 4) * 16);
        const uint32_t boffs = BI_OFF
                             + (uint32_t)((lane & 7) + ((lane >> 4) << 3)) * ROWPAD
                             + (uint32_t)(((lane >> 3) & 1) * 16);

        int acch[2][8][4], accl[2][8][4];
#pragma unroll
        for (int im = 0; im < 2; ++im)
#pragma unroll
            for (int jn = 0; jn < 8; ++jn)
#pragma unroll
                for (int r = 0; r < 4; ++r) { acch[im][jn][r] = 0; accl[im][jn][r] = 0; }

        ILOAD(0);
        ILOAD(1);

#pragma unroll 1
        for (int i = 0; i < KI_CHUNKS; ++i) {
            if (i + 2 < KI_CHUNKS) { ILOAD(i + 2); } else { CP_COMMIT(); }
            CP_WAIT2();
            BAR_INT();
            const uint32_t stg = sb + (i & 3) * ISTAGE;
#pragma unroll
            for (int kk = 0; kk < 2; ++kk) {
                uint32_t ah[2][4], al[2][4], bf[4][4];
                LDSM4(ah[0], stg + aoffs + kk * 32);
                LDSM4(ah[1], stg + aoffs + 16 * ROWPAD + kk * 32);
                LDSM4(al[0], stg + ALO_OFF + aoffs + kk * 32);
                LDSM4(al[1], stg + ALO_OFF + aoffs + 16 * ROWPAD + kk * 32);
#pragma unroll
                for (int j2 = 0; j2 < 4; ++j2)
                    LDSM4(bf[j2], stg + boffs + (uint32_t)(j2 * 16 * ROWPAD) + kk * 32);
#pragma unroll
                for (int im = 0; im < 2; ++im)
#pragma unroll
                    for (int j2 = 0; j2 < 4; ++j2) {
                        MMA_S8(acch[im][2 * j2],     ah[im], bf[j2][0], bf[j2][1]);
                        MMA_S8(acch[im][2 * j2 + 1], ah[im], bf[j2][2], bf[j2][3]);
                        MMA_S8(accl[im][2 * j2],     al[im], bf[j2][0], bf[j2][1]);
                        MMA_S8(accl[im][2 * j2 + 1], al[im], bf[j2][2], bf[j2][3]);
                    }
            }
        }
#undef ILOAD

        BAR_JOINT();   // fp warps have written F staging by now

        // ---- epilogue: out = scale*(rs*(128*hi+lo) + F) + bias ----
        const float* Fst = reinterpret_cast<const float*>(smem + IRING);
        const int ml0 = warpM * 32 + (lane >> 2);
        const int ncl = (lane & 3) * 2;
#pragma unroll
        for (int im = 0; im < 2; ++im) {
            const int mla = ml0 + im * 16;
            const int r0 = tm * 128 + mla;
            const int r1 = r0 + 8;
            const float rs0 = g_rs[r0];
            const float rs1 = g_rs[r1];
            float* o0 = out + (size_t)r0 * NTOT;
            float* o1 = out + (size_t)r1 * NTOT;
#pragma unroll
            for (int jn = 0; jn < 8; ++jn) {
                const int cl = ncl + jn * 8;
                const int c  = tn * 64 + cl;
                const float s0 = __ldg(scale + c), s1 = __ldg(scale + c + 1);
                const float b0 = __ldg(bias + c),  b1 = __ldg(bias + c + 1);
                const float2 F0 = *reinterpret_cast<const float2*>(Fst + mla * FPITCH + cl);
                const float2 F1 = *reinterpret_cast<const float2*>(Fst + (mla + 8) * FPITCH + cl);
                float2 v0, v1;
                v0.x = fmaf(s0, fmaf(rs0, fmaf(128.f, (float)acch[im][jn][0], (float)accl[im][jn][0]), F0.x), b0);
                v0.y = fmaf(s1, fmaf(rs0, fmaf(128.f, (float)acch[im][jn][1], (float)accl[im][jn][1]), F0.y), b1);
                v1.x = fmaf(s0, fmaf(rs1, fmaf(128.f, (float)acch[im][jn][2], (float)accl[im][jn][2]), F1.x), b0);
                v1.y = fmaf(s1, fmaf(rs1, fmaf(128.f, (float)acch[im][jn][3], (float)accl[im][jn][3]), F1.y), b1);
                *reinterpret_cast<float2*>(o0 + c) = v0;
                *reinterpret_cast<float2*>(o1 + c) = v1;
            }
        }
    } else {
        // ================= FP GROUP (warps 4-7), K [2816, 4096) k-pair packed =================
        const int f  = wid - 4;                   // warpF: m span f*32
        const int tf = tid - 128;                 // 0..127
        const int lkp  = tf >> 4;                 // 0..7 (k-pair row within stage)
        const int lsub = tf & 15;                 // 0..15
        const float2* pA = g_xp + (size_t)lkp * MTOT + tm * 128 + lsub * 8;
        const float2* pB = g_wp + (size_t)lkp * NTOT + tn * 64  + lsub * 4;
        const uint32_t sdA = (uint32_t)lkp * 1024 + (uint32_t)lsub * 64;
        const uint32_t sdB = FA_BYTES + (uint32_t)lkp * 512 + (uint32_t)lsub * 32;

#define FLOAD(J) do { \
        const uint32_t st_ = sb + FRING_OFF + ((J) & 3) * FSTAGE; \
        const float2* gA_ = pA + (size_t)(J) * (8 * MTOT); \
        const float2* gB_ = pB + (size_t)(J) * (8 * NTOT); \
        cpasync16(st_ + sdA +  0, gA_ + 0); \
        cpasync16(st_ + sdA + 16, gA_ + 2); \
        cpasync16(st_ + sdA + 32, gA_ + 4); \
        cpasync16(st_ + sdA + 48, gA_ + 6); \
        cpasync16(st_ + sdB +  0, gB_ + 0); \
        cpasync16(st_ + sdB + 16, gB_ + 2); \
        CP_COMMIT(); \
    } while (0)

        const int mg = lane >> 3;                 // 0..3 (8 m each)
        const int ng = lane & 7;                  // 0..7 (n = ng + 8j)
        const uint32_t aoff = (uint32_t)((f * 32 + mg * 8) * 8);   // bytes in kp row
        const uint32_t boff = FA_BYTES + (uint32_t)(ng * 8);

        uint64_t acc[8][8];                       // [mi][j], f32x2 (even-k, odd-k) sums
#pragma unroll
        for (int mi = 0; mi < 8; ++mi)
#pragma unroll
            for (int j = 0; j < 8; ++j) acc[mi][j] = 0ull;

        FLOAD(0);
        FLOAD(1);

#pragma unroll 1
        for (int s = 0; s < FPSTAGES; ++s) {
            if (s + 2 < FPSTAGES) { FLOAD(s + 2); } else { CP_COMMIT(); }
            CP_WAIT2();
            BAR_FP();
            const uint32_t stF = sb + FRING_OFF + (s & 3) * FSTAGE;
#pragma unroll
            for (int kp = 0; kp < 8; ++kp) {
                uint64_t a[8], b[8];
                const uint32_t ab = stF + (uint32_t)kp * 1024 + aoff;
                const uint32_t bb = stF + (uint32_t)kp * 512 + boff;
                LDS_V2U64(a[0], a[1], ab);
                LDS_V2U64(a[2], a[3], ab + 16);
                LDS_V2U64(a[4], a[5], ab + 32);
                LDS_V2U64(a[6], a[7], ab + 48);
#pragma unroll
                for (int j = 0; j < 8; ++j) LDS_U64(b[j], bb + (uint32_t)(j * 64));
#pragma unroll
                for (int mi = 0; mi < 8; ++mi)
#pragma unroll
                    for (int j = 0; j < 8; ++j)
                        FFMA2(acc[mi][j], a[mi], b[j]);
            }
        }
#undef FLOAD

        // ---- hadd + write F partials to staging [m][FPITCH] ----
#pragma unroll
        for (int mi = 0; mi < 8; ++mi) {
            const uint32_t rb = sb + IRING
                + (uint32_t)((f * 32 + mg * 8 + mi) * FPITCH + ng) * 4;
#pragma unroll
            for (int j = 0; j < 8; ++j) {
                float lo, hi;
                UNPACK2(lo, hi, acc[mi][j]);
                STS_F32(rb + (uint32_t)(j * 32), lo + hi);
            }
        }
        BAR_JOINT();
    }
}

// ---------------- Launch ----------------
extern "C" void kernel_launch(void* const* d_in, const int* in_sizes, int n_in,
                              void* d_out, int out_size) {
    (void)in_sizes; (void)n_in; (void)out_size;
    const float* x     = (const float*)d_in[0];   // [4,2048,4096] fp32
    const int*   wint  = (const int*)d_in[1];     // [16384,4096] int32
    const float* scale = (const float*)d_in[2];   // [16384,1] fp32
    const float* bias  = (const float*)d_in[3];   // [16384] fp32
    float* out = (float*)d_out;                   // [4,2048,16384] fp32

    quant_x_kernel<<<MTOT, 256>>>((const float4*)x);
    quant_w_kernel<<<(int)((size_t)NTOT * KTOT / 16 / 256), 256>>>((const int4*)wint);
    {
        dim3 g(KFP / 32, MTOT / 32);
        trans_xp_kernel<<<g, 256>>>(x);
    }
    {
        dim3 g(KFP / 32, NTOT / 32);
        trans_wp_kernel<<<g, 256>>>(wint);
    }

    cudaFuncSetAttribute(qlin_dual, cudaFuncAttributeMaxDynamicSharedMemorySize, SMEM_BYTES);
    qlin_dual<<<(MTOT / 128) * (NTOT / 64), 256, SMEM_BYTES>>>(out, scale, bias);
}